// round 16
// baseline (speedup 1.0000x reference)
#include <cuda_runtime.h>
#include <cuda_fp16.h>
#include <cstdint>

// ConvNeXt block: dwconv7x7 -> LN -> fused 1x1 MLP (fp16 mma.sync) -> residual
#define N_IMG 32
#define C_DIM 128
#define H_DIM 64
#define W_DIM 64
#define D_BOT 512
#define EPS_LN 1e-5f
#define M_TOT (N_IMG * H_DIM * W_DIM)   // 131072

// ---------------- scratch (device globals; no allocs) ----------------------
__device__ __half g_y[(size_t)M_TOT * C_DIM];
__device__ __half g_w1h[D_BOT * C_DIM];
__device__ __half g_w2h[C_DIM * D_BOT];

// ---------------- helpers ---------------------------------------------------
__device__ __forceinline__ uint32_t s2u(const void* p) {
    uint32_t a;
    asm("{ .reg .u64 t; cvta.to.shared.u64 t, %1; cvt.u32.u64 %0, t; }"
        : "=r"(a) : "l"(p));
    return a;
}
__device__ __forceinline__ void cpasync16(uint32_t dst, const void* src) {
    asm volatile("cp.async.cg.shared.global [%0], [%1], 16;" :: "r"(dst), "l"(src));
}
__device__ __forceinline__ void ldsm4(uint32_t* r, uint32_t addr) {
    asm volatile("ldmatrix.sync.aligned.m8n8.x4.shared.b16 {%0,%1,%2,%3}, [%4];"
                 : "=r"(r[0]), "=r"(r[1]), "=r"(r[2]), "=r"(r[3]) : "r"(addr));
}
__device__ __forceinline__ void mma_f16(float* c, uint32_t a0, uint32_t a1,
                                        uint32_t a2, uint32_t a3,
                                        uint32_t b0, uint32_t b1) {
    asm volatile(
        "mma.sync.aligned.m16n8k16.row.col.f32.f16.f16.f32 "
        "{%0,%1,%2,%3}, {%4,%5,%6,%7}, {%8,%9}, {%0,%1,%2,%3};"
        : "+f"(c[0]), "+f"(c[1]), "+f"(c[2]), "+f"(c[3])
        : "r"(a0), "r"(a1), "r"(a2), "r"(a3), "r"(b0), "r"(b1));
}
__device__ __forceinline__ uint32_t packh(__half a, __half b) {
    return (uint32_t)__half_as_ushort(a) | ((uint32_t)__half_as_ushort(b) << 16);
}
// ---- f32x2 packed-FMA helpers ----
__device__ __forceinline__ unsigned long long splat2(float x) {
    unsigned long long r;
    unsigned int xi = __float_as_uint(x);
    asm("mov.b64 %0, {%1, %1};" : "=l"(r) : "r"(xi));
    return r;
}
__device__ __forceinline__ unsigned long long pack2(float a, float b) {
    unsigned long long r;
    asm("mov.b64 %0, {%1, %2};" : "=l"(r) : "f"(a), "f"(b));
    return r;
}
__device__ __forceinline__ void ffma2(unsigned long long& d,
                                      unsigned long long a,
                                      unsigned long long b) {
    asm("fma.rn.f32x2 %0, %1, %2, %0;" : "+l"(d) : "l"(a), "l"(b));
}
__device__ __forceinline__ float2 u2f(unsigned long long u) {
    float2 f;
    asm("mov.b64 {%0, %1}, %2;" : "=f"(f.x), "=f"(f.y) : "l"(u));
    return f;
}

// ---------------------------------------------------------------------------
// Kernel 1: dwconv 7x7 + bias + LN -> fp16 NHWC, with dy-prefetch pipeline.
// Blocks >= 1024 instead perform the weight fp16 conversion (merged wconv).
// ---------------------------------------------------------------------------
#define DW_SY    (128 * 129)                 // floats
#define DWLN_SMEM (DW_SY * 4)                // 66048 B

__device__ __forceinline__ void dw_accum(
    const float4 v1, const float* wcur, const float* wprev,
    int l, int li, unsigned long long acc[4])
{
    float by = __shfl_sync(0xffffffffu, v1.y, (l - 1) & 31);
    float bz = __shfl_sync(0xffffffffu, v1.z, (l - 1) & 31);
    float bw = __shfl_sync(0xffffffffu, v1.w, (l - 1) & 31);
    float cx = __shfl_sync(0xffffffffu, v1.x, (l + 1) & 31);
    float cy = __shfl_sync(0xffffffffu, v1.y, (l + 1) & 31);
    float cz = __shfl_sync(0xffffffffu, v1.z, (l + 1) & 31);
    if (li == 0)  { by = 0.f; bz = 0.f; bw = 0.f; }
    if (li == 15) { cx = 0.f; cy = 0.f; cz = 0.f; }
    const float s[10] = {by, bz, bw, v1.x, v1.y, v1.z, v1.w, cx, cy, cz};
    unsigned long long sp[10];
    #pragma unroll
    for (int k = 0; k < 10; k++) sp[k] = splat2(s[k]);
    #pragma unroll
    for (int dx = 0; dx < 7; dx++) {
        const unsigned long long wp = pack2(wcur[dx], wprev[dx]);
        #pragma unroll
        for (int j = 0; j < 4; j++) ffma2(acc[j], sp[dx + j], wp);
    }
}

__global__ __launch_bounds__(256, 3) void dwln_kernel(
    const float* __restrict__ x, const float* __restrict__ dw_w,
    const float* __restrict__ dw_b, const float* __restrict__ gamma,
    const float* __restrict__ beta,
    const float* __restrict__ w1, const float* __restrict__ w2)
{
    extern __shared__ float s_y[];      // [128 pos][129]

    const int b = blockIdx.x;
    if (b >= 1024) {                    // merged weight conversion
        const int i = (b - 1024) * 256 + threadIdx.x;
        if (i < D_BOT * C_DIM) {
            g_w1h[i] = __float2half(w1[i]);
            g_w2h[i] = __float2half(w2[i]);
        }
        return;
    }

    const int n  = b >> 5;
    const int h0 = (b & 31) << 1;
    const int tid = threadIdx.x;
    const int wg = tid >> 5;
    const int l  = tid & 31;
    const int half = l >> 4;
    const int li = l & 15;
    const int slot = wg * 2 + half;

    #pragma unroll 1
    for (int it = 0; it < 4; it++) {
        const int c0 = it * 32 + slot;
        const int c1 = c0 + 16;
        const float* xc0 = x + ((size_t)n * C_DIM + c0) * (H_DIM * W_DIM);
        const float* xc1 = x + ((size_t)n * C_DIM + c1) * (H_DIM * W_DIM);
        const float* wq0 = dw_w + c0 * 49;
        const float* wq1 = dw_w + c1 * 49;

        unsigned long long acc0[4], acc1[4];
        {
            const float bi0 = __ldg(&dw_b[c0]);
            const float bi1 = __ldg(&dw_b[c1]);
            #pragma unroll
            for (int j = 0; j < 4; j++) { acc0[j] = splat2(bi0); acc1[j] = splat2(bi1); }
        }
        float wprev0[7], wprev1[7];
        #pragma unroll
        for (int k = 0; k < 7; k++) { wprev0[k] = 0.f; wprev1[k] = 0.f; }

        // prefetch dy = 0  (hh = h0-3; always out of range iff h0 < 3)
        float4 pa = make_float4(0.f, 0.f, 0.f, 0.f);
        float4 pb = pa;
        {
            const int hh = h0 - 3;
            if (hh >= 0) {
                pa = *reinterpret_cast<const float4*>(xc0 + hh * W_DIM + 4 * li);
                pb = *reinterpret_cast<const float4*>(xc1 + hh * W_DIM + 4 * li);
            }
        }

        #pragma unroll 1
        for (int dy = 0; dy < 8; dy++) {
            const float4 ca = pa, cb = pb;
            // prefetch dy+1 before consuming dy
            if (dy < 7) {
                const int hh = h0 - 2 + dy;
                pa = make_float4(0.f, 0.f, 0.f, 0.f);
                pb = pa;
                if (hh >= 0 && hh < H_DIM) {
                    pa = *reinterpret_cast<const float4*>(xc0 + hh * W_DIM + 4 * li);
                    pb = *reinterpret_cast<const float4*>(xc1 + hh * W_DIM + 4 * li);
                }
            }
            float wcur0[7], wcur1[7];
            #pragma unroll
            for (int k = 0; k < 7; k++) {
                wcur0[k] = (dy < 7) ? __ldg(&wq0[dy * 7 + k]) : 0.f;
                wcur1[k] = (dy < 7) ? __ldg(&wq1[dy * 7 + k]) : 0.f;
            }
            dw_accum(ca, wcur0, wprev0, l, li, acc0);
            dw_accum(cb, wcur1, wprev1, l, li, acc1);
            #pragma unroll
            for (int k = 0; k < 7; k++) { wprev0[k] = wcur0[k]; wprev1[k] = wcur1[k]; }
        }
        #pragma unroll
        for (int j = 0; j < 4; j++) {
            const float2 f0 = u2f(acc0[j]);
            const float2 f1 = u2f(acc1[j]);
            s_y[(4 * li + j) * 129 + c0]      = f0.x;
            s_y[(64 + 4 * li + j) * 129 + c0] = f0.y;
            s_y[(4 * li + j) * 129 + c1]      = f1.x;
            s_y[(64 + 4 * li + j) * 129 + c1] = f1.y;
        }
    }
    __syncthreads();

    for (int wi = 0; wi < 16; wi++) {
        const int p = wg * 16 + wi;
        float v[4], s = 0.f, sq = 0.f;
        #pragma unroll
        for (int i = 0; i < 4; i++) {
            v[i] = s_y[p * 129 + l + 32 * i];
            s += v[i];
            sq += v[i] * v[i];
        }
        #pragma unroll
        for (int o = 16; o > 0; o >>= 1) {
            s  += __shfl_xor_sync(0xffffffffu, s, o);
            sq += __shfl_xor_sync(0xffffffffu, sq, o);
        }
        const float mu  = s * (1.f / 128.f);
        const float var = sq * (1.f / 128.f) - mu * mu;
        const float rs  = rsqrtf(var + EPS_LN);
        const size_t row =
            (((size_t)n * H_DIM + h0 + (p >> 6)) * W_DIM + (p & 63)) * C_DIM;
        #pragma unroll
        for (int i = 0; i < 4; i++) {
            const int cix = l + 32 * i;
            const float val = (v[i] - mu) * rs * __ldg(&gamma[cix]) + __ldg(&beta[cix]);
            g_y[row + cix] = __float2half(val);
        }
    }
}

// ---------------------------------------------------------------------------
// Fused MLP v3 (unchanged from R15): 4-deep B ring, one __syncthreads/phase.
// ---------------------------------------------------------------------------
#define ROWB  144
#define ROWY  272
#define BMAT  (128 * ROWB)          // 18432 B
#define Y_OFF (4 * BMAT)            // 73728
#define H_OFF (Y_OFF + 64 * ROWY)   // 91136
#define SMEM_F (H_OFF + 64 * 256)   // 107520

__device__ __forceinline__ void stage_y(int m0, uint32_t yb) {
    const int tid = threadIdx.x;
    #pragma unroll
    for (int p = 0; p < 4; p++) {
        const int idx = p * 256 + tid;          // 0..1023
        const int row = idx >> 4, seg = idx & 15;
        cpasync16(yb + row * ROWY + seg * 16,
                  g_y + (size_t)(m0 + row) * C_DIM + seg * 8);
    }
}

__device__ __forceinline__ void stage_B(int t, uint32_t buf) {
    const int tid = threadIdx.x;
    const int jc = t >> 2, s = t & 3;
    const __half* src;
    int k0;
    if (s < 2) { src = g_w1h + (size_t)(jc * 128) * C_DIM; k0 = s * 64; }
    else       { src = g_w2h;                              k0 = jc * 128 + (s - 2) * 64; }
    const int ld = (s < 2) ? C_DIM : D_BOT;
    #pragma unroll
    for (int p = 0; p < 4; p++) {
        const int idx = p * 256 + tid;
        const int row = idx >> 3, seg = idx & 7;
        cpasync16(buf + row * ROWB + seg * 16,
                  src + (size_t)row * ld + k0 + seg * 8);
    }
}

__device__ __forceinline__ void chunk1(uint32_t yb, int aCol, uint32_t bBase,
                                       int wm, int wn, int lane, float c[2][4][4])
{
    #pragma unroll
    for (int ks = 0; ks < 4; ks++) {
        const uint32_t aAddr = yb + (wm * 32 + (lane & 15)) * ROWY +
                               aCol + ks * 32 + (lane >> 4) * 16;
        const uint32_t bAddr = bBase +
                               (wn * 32 + (lane & 7) + (lane >> 4) * 8) * ROWB +
                               ks * 32 + ((lane >> 3) & 1) * 16;
        uint32_t Af[2][4], Bf[2][4];
        #pragma unroll
        for (int mf = 0; mf < 2; mf++) ldsm4(Af[mf], aAddr + mf * (16 * ROWY));
        #pragma unroll
        for (int n2 = 0; n2 < 2; n2++) ldsm4(Bf[n2], bAddr + n2 * (16 * ROWB));
        #pragma unroll
        for (int mf = 0; mf < 2; mf++)
            #pragma unroll
            for (int nf = 0; nf < 4; nf++)
                mma_f16(c[mf][nf], Af[mf][0], Af[mf][1], Af[mf][2], Af[mf][3],
                        Bf[nf >> 1][(nf & 1) * 2], Bf[nf >> 1][(nf & 1) * 2 + 1]);
    }
}

__device__ __forceinline__ void chunk2h(uint32_t bBase, uint32_t hb, int kc,
                                        int wm, int wn, int lane, float c[2][4][4])
{
    #pragma unroll
    for (int ks = 0; ks < 4; ks++) {
        const int blk = kc * 8 + ks * 2 + (lane >> 4);
        const uint32_t aAddr0 = hb + (wm * 32 + (lane & 15)) * 256 +
                                (uint32_t)((blk ^ (lane & 7)) << 4);
        const uint32_t bAddr = bBase +
                               (wn * 32 + (lane & 7) + (lane >> 4) * 8) * ROWB +
                               ks * 32 + ((lane >> 3) & 1) * 16;
        uint32_t Af[2][4], Bf[2][4];
        #pragma unroll
        for (int mf = 0; mf < 2; mf++) ldsm4(Af[mf], aAddr0 + mf * (16 * 256));
        #pragma unroll
        for (int n2 = 0; n2 < 2; n2++) ldsm4(Bf[n2], bAddr + n2 * (16 * ROWB));
        #pragma unroll
        for (int mf = 0; mf < 2; mf++)
            #pragma unroll
            for (int nf = 0; nf < 4; nf++)
                mma_f16(c[mf][nf], Af[mf][0], Af[mf][1], Af[mf][2], Af[mf][3],
                        Bf[nf >> 1][(nf & 1) * 2], Bf[nf >> 1][(nf & 1) * 2 + 1]);
    }
}

__global__ __launch_bounds__(256, 2) void fused_mlp(
    const float* __restrict__ x, const float* __restrict__ b1,
    const float* __restrict__ b2, float* __restrict__ out)
{
    extern __shared__ char dsm[];
    const uint32_t sb = s2u(dsm);
    const uint32_t yb = sb + Y_OFF;
    const uint32_t hb = sb + H_OFF;

    const int tid = threadIdx.x;
    const int wid = tid >> 5, lane = tid & 31;
    const int wm = wid >> 2, wn = wid & 3;
    const int r = lane >> 2, q = lane & 3;
    const int m0 = blockIdx.x << 6;

    float c1[2][4][4], c2[2][4][4];
    #pragma unroll
    for (int a = 0; a < 2; a++)
        #pragma unroll
        for (int b_ = 0; b_ < 4; b_++)
            #pragma unroll
            for (int d = 0; d < 4; d++) { c1[a][b_][d] = 0.f; c2[a][b_][d] = 0.f; }

    stage_y(m0, yb);
    asm volatile("cp.async.commit_group;");
    stage_B(0, sb);
    asm volatile("cp.async.commit_group;");
    stage_B(1, sb + BMAT);
    asm volatile("cp.async.commit_group;");

    #pragma unroll 1
    for (int t = 0; t < 16; t++) {
        if (t + 2 < 16) {
            stage_B(t + 2, sb + ((t + 2) & 3) * BMAT);
            asm volatile("cp.async.commit_group;");
            asm volatile("cp.async.wait_group 2;");
        } else if (t + 2 == 16) {
            asm volatile("cp.async.wait_group 1;");
        } else {
            asm volatile("cp.async.wait_group 0;");
        }
        __syncthreads();                       // single barrier per phase
        const uint32_t buf = sb + (t & 3) * BMAT;
        const int jc = t >> 2, s = t & 3;
        if (s < 2) {
            chunk1(yb, s * 128, buf, wm, wn, lane, c1);
            if (s == 1) {
                #pragma unroll
                for (int nf = 0; nf < 4; nf++) {
                    const int col = wn * 32 + nf * 8 + 2 * q;      // 0..127
                    const float2 bb = *reinterpret_cast<const float2*>(
                        b1 + jc * 128 + col);
                    const int blkc = col >> 3;
                    #pragma unroll
                    for (int mf = 0; mf < 2; mf++)
                        #pragma unroll
                        for (int hf = 0; hf < 2; hf++) {
                            const int row = wm * 32 + mf * 16 + r + 8 * hf;
                            const float v0 = fmaxf(c1[mf][nf][2 * hf]     + bb.x, 0.f);
                            const float v1 = fmaxf(c1[mf][nf][2 * hf + 1] + bb.y, 0.f);
                            const uint32_t ad = hb + row * 256 +
                                ((uint32_t)(blkc ^ (row & 7)) << 4) + ((col * 2) & 15);
                            asm volatile("st.shared.b32 [%0], %1;" ::
                                "r"(ad), "r"(packh(__float2half(v0), __float2half(v1)))
                                : "memory");
                            c1[mf][nf][2 * hf] = 0.f;
                            c1[mf][nf][2 * hf + 1] = 0.f;
                        }
                }
            }
        } else {
            chunk2h(buf, hb, s - 2, wm, wn, lane, c2);
        }
    }
    __syncthreads();

    // ---- final epilogue: transpose via smem, NCHW store + bias + residual ----
    float* sC = (float*)dsm;                  // 64 ch x 68 floats per half
    const int n  = m0 >> 12;
    const int sp0 = m0 & 4095;

    #pragma unroll 1
    for (int hh = 0; hh < 2; hh++) {
        if ((wn >> 1) == hh) {
            #pragma unroll
            for (int nf = 0; nf < 4; nf++) {
                const int cl = (wn & 1) * 32 + nf * 8 + 2 * q;
                #pragma unroll
                for (int mf = 0; mf < 2; mf++)
                    #pragma unroll
                    for (int hf = 0; hf < 2; hf++) {
                        const int ml = wm * 32 + mf * 16 + r + 8 * hf;
                        sC[cl * 68 + ml]       = c2[mf][nf][2 * hf];
                        sC[(cl + 1) * 68 + ml] = c2[mf][nf][2 * hf + 1];
                    }
            }
        }
        __syncthreads();
        #pragma unroll
        for (int qi = 0; qi < 4; qi++) {
            const int idx = qi * 256 + tid;
            const int j   = idx >> 4;          // 0..63
            const int m4  = (idx & 15) << 2;   // 0..60
            const int ch  = hh * 64 + j;
            const float bc = __ldg(&b2[ch]);
            const size_t g = ((size_t)(n * C_DIM + ch) << 12) + sp0 + m4;
            float4 v  = *reinterpret_cast<const float4*>(&sC[j * 68 + m4]);
            float4 xv = *reinterpret_cast<const float4*>(x + g);
            float4 o;
            o.x = v.x + xv.x + bc;
            o.y = v.y + xv.y + bc;
            o.z = v.z + xv.z + bc;
            o.w = v.w + xv.w + bc;
            *reinterpret_cast<float4*>(out + g) = o;
        }
        __syncthreads();
    }
}

// ---------------------------------------------------------------------------
extern "C" void kernel_launch(void* const* d_in, const int* in_sizes, int n_in,
                              void* d_out, int out_size)
{
    const float* x     = (const float*)d_in[0];
    const float* dw_w  = (const float*)d_in[1];
    const float* dw_b  = (const float*)d_in[2];
    const float* gamma = (const float*)d_in[3];
    const float* beta  = (const float*)d_in[4];
    const float* pw1_w = (const float*)d_in[5];
    const float* pw1_b = (const float*)d_in[6];
    const float* pw2_w = (const float*)d_in[7];
    const float* pw2_b = (const float*)d_in[8];
    float* out = (float*)d_out;

    static bool attr_done = false;
    if (!attr_done) {
        cudaFuncSetAttribute(dwln_kernel, cudaFuncAttributeMaxDynamicSharedMemorySize, DWLN_SMEM);
        cudaFuncSetAttribute(fused_mlp, cudaFuncAttributeMaxDynamicSharedMemorySize, SMEM_F);
        attr_done = true;
    }

    dwln_kernel<<<1024 + 256, 256, DWLN_SMEM>>>(x, dw_w, dw_b, gamma, beta,
                                                pw1_w, pw2_w);
    fused_mlp<<<M_TOT / 64, 256, SMEM_F>>>(x, pw1_b, pw2_b, out);
}